// round 16
// baseline (speedup 1.0000x reference)
#include <cuda_runtime.h>

// ---------------------------------------------------------------------------
// BEVHDMapFusionNet — round 15:
//  - attention: register diet -> 3 blocks/SM. Fused exp+PV per key (drops
//    s[16]x2 score arrays), Q pre-scaled in qkv, __launch_bounds__(128,3).
//  - rest identical to 479us baseline.
// ---------------------------------------------------------------------------

#define BT 8
#define HW 1024

typedef unsigned long long u64;

__device__ __forceinline__ u64 pack2(float lo, float hi) {
    u64 r; asm("mov.b64 %0, {%1, %2};" : "=l"(r) : "f"(lo), "f"(hi)); return r;
}
__device__ __forceinline__ void unpack2(u64 v, float& lo, float& hi) {
    asm("mov.b64 {%0, %1}, %2;" : "=f"(lo), "=f"(hi) : "l"(v));
}
__device__ __forceinline__ void ffma2(u64& d, u64 a, u64 b) {
    asm("fma.rn.f32x2 %0, %1, %2, %0;" : "+l"(d) : "l"(a), "l"(b));
}
__device__ __forceinline__ u64 mul2(u64 a, u64 b) {
    u64 r; asm("mul.rn.f32x2 %0, %1, %2;" : "=l"(r) : "l"(a), "l"(b)); return r;
}
__device__ __forceinline__ u64 add2(u64 a, u64 b) {
    u64 r; asm("add.rn.f32x2 %0, %1, %2;" : "=l"(r) : "l"(a), "l"(b)); return r;
}

__device__ float g_bev_feat[BT * 128 * HW];  // NCHW
__device__ float g_kv[BT * 192 * HW];        // ch 0..127 hd_feat, 128..191 front
__device__ float g_q[BT * HW * 128];         // PRE-SCALED by 32^-0.5
__device__ float g_k[BT * HW * 128];
__device__ float g_v[BT * HW * 128];
__device__ float g_attn[BT * HW * 128];
__device__ float g_fused[BT * 128 * HW];
__device__ float g_po[BT * 4 * 8 * 32 * 1024];   // split-K partials [bt][h][ck][d][n]
__device__ float g_pl[BT * 4 * 8 * 1024];        // l per row per chunk

// transposed weights
__device__ float g_wq_t[128 * 128];   // [k][o]
__device__ float g_wk_t[192 * 128];
__device__ float g_wv_t[192 * 128];
__device__ float g_wo_t[128 * 128];
__device__ float g_wbev_t[144 * 9 * 128];  // [(c*9+k)*128 + oc]
__device__ float g_whd_t[64 * 9 * 128];
__device__ float g_wout_t[144 * 9 * 128];

// ---------------------------------------------------------------------------
// ONE fused weight-transform kernel.
// ---------------------------------------------------------------------------
#define N_WQ   16384
#define N_WK   24576
#define N_WV   24576
#define N_WO   16384
#define N_WBEV 165888
#define N_WHD  73728
#define N_WOUT 165888

__global__ void __launch_bounds__(256) transform_all_kernel(
    const float* __restrict__ wq, const float* __restrict__ wk,
    const float* __restrict__ wv, const float* __restrict__ wo,
    const float* __restrict__ wbev, const float* __restrict__ whd,
    const float* __restrict__ wout)
{
    int idx = blockIdx.x * 256 + threadIdx.x;
    if (idx < N_WQ) {
        int o = idx & 127, k = idx >> 7;
        g_wq_t[idx] = wq[o * 128 + k];
        return;
    }
    idx -= N_WQ;
    if (idx < N_WK) {
        int o = idx & 127, k = idx >> 7;
        g_wk_t[idx] = wk[o * 192 + k];
        return;
    }
    idx -= N_WK;
    if (idx < N_WV) {
        int o = idx & 127, k = idx >> 7;
        g_wv_t[idx] = wv[o * 192 + k];
        return;
    }
    idx -= N_WV;
    if (idx < N_WO) {
        int o = idx & 127, k = idx >> 7;
        g_wo_t[idx] = wo[o * 128 + k];
        return;
    }
    idx -= N_WO;
    if (idx < N_WBEV) {
        int oc = idx & 127, rem = idx >> 7;
        int k = rem % 9, c = rem / 9;
        g_wbev_t[idx] = wbev[(oc * 144 + c) * 9 + k];
        return;
    }
    idx -= N_WBEV;
    if (idx < N_WHD) {
        int oc = idx & 127, rem = idx >> 7;
        int k = rem % 9, c = rem / 9;
        g_whd_t[idx] = whd[(oc * 64 + c) * 9 + k];
        return;
    }
    idx -= N_WHD;
    if (idx < N_WOUT) {
        int oc = idx & 127, rem = idx >> 7;
        int k = rem % 9, c = rem / 9;
        g_wout_t[idx] = wout[(oc * 144 + c) * 9 + k];
        return;
    }
}

// ---------------------------------------------------------------------------
// Conv 3x3 SAME + bias + relu, 2 adjacent y-pixels per thread, 8 oc/thread.
// ---------------------------------------------------------------------------
template<int CIN_MAIN, int CIN_TOT>
__device__ __forceinline__ void conv_body(
    const float* __restrict__ in, const float* __restrict__ ego,
    const float* __restrict__ wt, const float* __restrict__ bias,
    float* __restrict__ out, int out_ctot,
    int bt, int oc0, int y0,
    float (&s_in)[16][18][34], float (&s_w)[16][9][8])
{
    const int tid = threadIdx.x;
    const int tx  = tid & 31, ty = tid >> 5;

    u64 acc[2][4];
#pragma unroll
    for (int p = 0; p < 2; p++)
#pragma unroll
        for (int i = 0; i < 4; i++) acc[p][i] = 0ull;

    for (int c0 = 0; c0 < CIN_TOT; c0 += 16) {
        for (int idx = tid; idx < 16 * 18 * 34; idx += 256) {
            int ic  = idx / 612;
            int rem = idx - ic * 612;
            int yy  = rem / 34, xx = rem - yy * 34;
            int gy  = y0 + yy - 1, gx = xx - 1;
            int c   = c0 + ic;
            float v = 0.f;
            if ((unsigned)gy < 32u && (unsigned)gx < 32u) {
                if (CIN_MAIN == CIN_TOT || c < CIN_MAIN)
                    v = in[((bt * CIN_MAIN + c) << 10) + (gy << 5) + gx];
                else
                    v = ego[(bt << 4) + (c - CIN_MAIN)];
            }
            s_in[ic][yy][xx] = v;
        }
        for (int idx = tid; idx < 16 * 9 * 8; idx += 256) {
            int oc  = idx & 7;
            int rem = idx >> 3;
            int k   = rem % 9, ic = rem / 9;
            s_w[ic][k][oc] = wt[((c0 + ic) * 9 + k) * 128 + oc0 + oc];
        }
        __syncthreads();

#pragma unroll 2
        for (int ic = 0; ic < 16; ic++) {
            float v[4][3];
#pragma unroll
            for (int ry = 0; ry < 4; ry++)
#pragma unroll
                for (int rx = 0; rx < 3; rx++)
                    v[ry][rx] = s_in[ic][2 * ty + ry][tx + rx];
#pragma unroll
            for (int ky = 0; ky < 3; ky++)
#pragma unroll
                for (int kx = 0; kx < 3; kx++) {
                    const ulonglong2* wp = (const ulonglong2*)s_w[ic][ky * 3 + kx];
                    ulonglong2 w01 = wp[0], w23 = wp[1];
                    u64 vk0 = pack2(v[ky][kx], v[ky][kx]);
                    u64 vk1 = pack2(v[ky + 1][kx], v[ky + 1][kx]);
                    ffma2(acc[0][0], vk0, w01.x); ffma2(acc[0][1], vk0, w01.y);
                    ffma2(acc[0][2], vk0, w23.x); ffma2(acc[0][3], vk0, w23.y);
                    ffma2(acc[1][0], vk1, w01.x); ffma2(acc[1][1], vk1, w01.y);
                    ffma2(acc[1][2], vk1, w23.x); ffma2(acc[1][3], vk1, w23.y);
                }
        }
        __syncthreads();
    }

#pragma unroll
    for (int p = 0; p < 2; p++) {
        const int y = y0 + 2 * ty + p;
#pragma unroll
        for (int q = 0; q < 4; q++) {
            float f0, f1;
            unpack2(acc[p][q], f0, f1);
            int oc = oc0 + 2 * q;
            out[((bt * out_ctot + oc) << 10) + (y << 5) + tx] =
                fmaxf(f0 + bias[oc], 0.f);
            out[((bt * out_ctot + oc + 1) << 10) + (y << 5) + tx] =
                fmaxf(f1 + bias[oc + 1], 0.f);
        }
    }
}

// ---------------------------------------------------------------------------
// Fused frontend: grid (8, 33, 2).
// ---------------------------------------------------------------------------
__global__ void __launch_bounds__(256) frontend_kernel(
    const float* __restrict__ bev, const float* __restrict__ hd,
    const float* __restrict__ ego, const float* __restrict__ front,
    const float* __restrict__ b_bev, const float* __restrict__ b_hd)
{
    __shared__ __align__(16) float s_in[16][18][34];
    __shared__ __align__(16) float s_w[16][9][8];

    const int y = blockIdx.y;
    if (y < 16) {
        conv_body<128, 144>(bev, ego, g_wbev_t, b_bev, g_bev_feat, 128,
                            blockIdx.x, y << 3, blockIdx.z << 4, s_in, s_w);
    } else if (y < 32) {
        conv_body<64, 64>(hd, nullptr, g_whd_t, b_hd, g_kv, 192,
                          blockIdx.x, (y - 16) << 3, blockIdx.z << 4, s_in, s_w);
    } else {
        int base = ((blockIdx.z << 3) + blockIdx.x) * 256 + threadIdx.x;
#pragma unroll 4
        for (int it = 0; it < 128; it++) {
            int idx = base + it * 4096;
            int x = idx & 31, yy = (idx >> 5) & 31, c = (idx >> 10) & 63, bt = idx >> 16;
            float fy = yy * 0.5f - 0.25f, fx = x * 0.5f - 0.25f;
            int y0 = (int)floorf(fy), x0 = (int)floorf(fx);
            float wy = fy - (float)y0, wx = fx - (float)x0;
            int y0c = max(y0, 0), y1c = min(y0 + 1, 15);
            int x0c = max(x0, 0), x1c = min(x0 + 1, 15);
            const float* basep = &front[(bt * 64 + c) << 8];
            float v00 = basep[(y0c << 4) + x0c], v01 = basep[(y0c << 4) + x1c];
            float v10 = basep[(y1c << 4) + x0c], v11 = basep[(y1c << 4) + x1c];
            float v = (1.f - wy) * ((1.f - wx) * v00 + wx * v01)
                    + wy * ((1.f - wx) * v10 + wx * v11);
            g_kv[((bt * 192 + 128 + c) << 10) + (yy << 5) + x] = v;
        }
    }
}

// ---------------------------------------------------------------------------
// qkv: y==0 -> fused K+V projection; y==1 -> Q projection (scaled by 32^-0.5).
// ---------------------------------------------------------------------------
__global__ void __launch_bounds__(256) qkv_kernel()
{
    __shared__ __align__(16) float s_A[2][16][68];
    __shared__ __align__(16) float s_B1[2][16][128];
    __shared__ __align__(16) float s_B2[2][16][128];

    const int tid  = threadIdx.x;
    const int mblk = blockIdx.x;
    const int bt   = mblk >> 4;
    const int nloc = (mblk & 15) << 6;
    const int tm = tid & 15, tn = tid >> 4;
    const int m0 = tm << 2, o0 = tn << 3;
    const int akk = tid >> 4, aj = tid & 15;
    const int bkk = tid >> 4, bj = tid & 15;

    if (blockIdx.y == 0) {
        const float* A = g_kv;
        const int K = 192, NC = 12;
        u64 acck[4][4], accv[4][4];
#pragma unroll
        for (int i = 0; i < 4; i++)
#pragma unroll
            for (int j = 0; j < 4; j++) { acck[i][j] = 0ull; accv[i][j] = 0ull; }

        {
            float4 t = *(const float4*)&A[((bt * K + akk) << 10) + nloc + (aj << 2)];
            *(float4*)&s_A[0][akk][aj << 2] = t;
            float4 k0 = *(const float4*)&g_wk_t[bkk * 128 + (bj << 2)];
            float4 k1 = *(const float4*)&g_wk_t[bkk * 128 + 64 + (bj << 2)];
            float4 v0 = *(const float4*)&g_wv_t[bkk * 128 + (bj << 2)];
            float4 v1 = *(const float4*)&g_wv_t[bkk * 128 + 64 + (bj << 2)];
            *(float4*)&s_B1[0][bkk][bj << 2] = k0;
            *(float4*)&s_B1[0][bkk][64 + (bj << 2)] = k1;
            *(float4*)&s_B2[0][bkk][bj << 2] = v0;
            *(float4*)&s_B2[0][bkk][64 + (bj << 2)] = v1;
        }
        __syncthreads();

        int buf = 0;
        for (int t = 0; t < NC; t++) {
            float4 pA, pK0, pK1, pV0, pV1;
            if (t < NC - 1) {
                int c0 = (t + 1) << 4;
                pA  = *(const float4*)&A[((bt * K + c0 + akk) << 10) + nloc + (aj << 2)];
                pK0 = *(const float4*)&g_wk_t[(c0 + bkk) * 128 + (bj << 2)];
                pK1 = *(const float4*)&g_wk_t[(c0 + bkk) * 128 + 64 + (bj << 2)];
                pV0 = *(const float4*)&g_wv_t[(c0 + bkk) * 128 + (bj << 2)];
                pV1 = *(const float4*)&g_wv_t[(c0 + bkk) * 128 + 64 + (bj << 2)];
            }

#pragma unroll
            for (int kk = 0; kk < 16; kk++) {
                float4 a0 = *(const float4*)&s_A[buf][kk][m0];
                ulonglong2 bk01 = *(const ulonglong2*)&s_B1[buf][kk][o0];
                ulonglong2 bk23 = *(const ulonglong2*)&s_B1[buf][kk][o0 + 4];
                ulonglong2 bv01 = *(const ulonglong2*)&s_B2[buf][kk][o0];
                ulonglong2 bv23 = *(const ulonglong2*)&s_B2[buf][kk][o0 + 4];
                u64 ap[4];
                ap[0] = pack2(a0.x, a0.x); ap[1] = pack2(a0.y, a0.y);
                ap[2] = pack2(a0.z, a0.z); ap[3] = pack2(a0.w, a0.w);
#pragma unroll
                for (int i = 0; i < 4; i++) {
                    ffma2(acck[i][0], ap[i], bk01.x);
                    ffma2(acck[i][1], ap[i], bk01.y);
                    ffma2(acck[i][2], ap[i], bk23.x);
                    ffma2(acck[i][3], ap[i], bk23.y);
                    ffma2(accv[i][0], ap[i], bv01.x);
                    ffma2(accv[i][1], ap[i], bv01.y);
                    ffma2(accv[i][2], ap[i], bv23.x);
                    ffma2(accv[i][3], ap[i], bv23.y);
                }
            }

            if (t < NC - 1) {
                int nb = buf ^ 1;
                *(float4*)&s_A[nb][akk][aj << 2] = pA;
                *(float4*)&s_B1[nb][bkk][bj << 2] = pK0;
                *(float4*)&s_B1[nb][bkk][64 + (bj << 2)] = pK1;
                *(float4*)&s_B2[nb][bkk][bj << 2] = pV0;
                *(float4*)&s_B2[nb][bkk][64 + (bj << 2)] = pV1;
            }
            __syncthreads();
            buf ^= 1;
        }

#pragma unroll
        for (int i = 0; i < 4; i++) {
            ulonglong2 tk0 = {acck[i][0], acck[i][1]};
            ulonglong2 tk1 = {acck[i][2], acck[i][3]};
            ulonglong2 tv0 = {accv[i][0], accv[i][1]};
            ulonglong2 tv1 = {accv[i][2], accv[i][3]};
            ulonglong2* kp = (ulonglong2*)&g_k[(bt * 1024 + nloc + m0 + i) * 128 + o0];
            ulonglong2* vp = (ulonglong2*)&g_v[(bt * 1024 + nloc + m0 + i) * 128 + o0];
            kp[0] = tk0; kp[1] = tk1;
            vp[0] = tv0; vp[1] = tv1;
        }
    } else {
        const float* A = g_bev_feat;
        const int K = 128, NC = 8;
        u64 acc2[4][4];
#pragma unroll
        for (int i = 0; i < 4; i++)
#pragma unroll
            for (int j = 0; j < 4; j++) acc2[i][j] = 0ull;

        {
            float4 t = *(const float4*)&A[((bt * K + akk) << 10) + nloc + (aj << 2)];
            *(float4*)&s_A[0][akk][aj << 2] = t;
            float4 t0 = *(const float4*)&g_wq_t[bkk * 128 + (bj << 2)];
            float4 t1 = *(const float4*)&g_wq_t[bkk * 128 + 64 + (bj << 2)];
            *(float4*)&s_B1[0][bkk][bj << 2] = t0;
            *(float4*)&s_B1[0][bkk][64 + (bj << 2)] = t1;
        }
        __syncthreads();

        int buf = 0;
        for (int t = 0; t < NC; t++) {
            float4 pA, pB0, pB1;
            if (t < NC - 1) {
                int c0 = (t + 1) << 4;
                pA  = *(const float4*)&A[((bt * K + c0 + akk) << 10) + nloc + (aj << 2)];
                pB0 = *(const float4*)&g_wq_t[(c0 + bkk) * 128 + (bj << 2)];
                pB1 = *(const float4*)&g_wq_t[(c0 + bkk) * 128 + 64 + (bj << 2)];
            }

#pragma unroll
            for (int kk = 0; kk < 16; kk++) {
                float4 a0 = *(const float4*)&s_A[buf][kk][m0];
                ulonglong2 b01 = *(const ulonglong2*)&s_B1[buf][kk][o0];
                ulonglong2 b23 = *(const ulonglong2*)&s_B1[buf][kk][o0 + 4];
                u64 ap[4];
                ap[0] = pack2(a0.x, a0.x); ap[1] = pack2(a0.y, a0.y);
                ap[2] = pack2(a0.z, a0.z); ap[3] = pack2(a0.w, a0.w);
#pragma unroll
                for (int i = 0; i < 4; i++) {
                    ffma2(acc2[i][0], ap[i], b01.x);
                    ffma2(acc2[i][1], ap[i], b01.y);
                    ffma2(acc2[i][2], ap[i], b23.x);
                    ffma2(acc2[i][3], ap[i], b23.y);
                }
            }

            if (t < NC - 1) {
                int nb = buf ^ 1;
                *(float4*)&s_A[nb][akk][aj << 2] = pA;
                *(float4*)&s_B1[nb][bkk][bj << 2] = pB0;
                *(float4*)&s_B1[nb][bkk][64 + (bj << 2)] = pB1;
            }
            __syncthreads();
            buf ^= 1;
        }

        // fold softmax scale 32^-0.5 into Q here
        const u64 sc2 = pack2(0.17677669529663687f, 0.17677669529663687f);
#pragma unroll
        for (int i = 0; i < 4; i++) {
            ulonglong2 t0 = {mul2(acc2[i][0], sc2), mul2(acc2[i][1], sc2)};
            ulonglong2 t1 = {mul2(acc2[i][2], sc2), mul2(acc2[i][3], sc2)};
            ulonglong2* op = (ulonglong2*)&g_q[(bt * 1024 + nloc + m0 + i) * 128 + o0];
            op[0] = t0; op[1] = t1;
        }
    }
}

// ---------------------------------------------------------------------------
// O-projection GEMM.
// ---------------------------------------------------------------------------
__global__ void __launch_bounds__(256) oproj_kernel(const float* __restrict__ bo)
{
    __shared__ __align__(16) float s_A[2][16][68];
    __shared__ __align__(16) float s_B[2][16][128];
    const float* A  = g_attn;
    const float* Wt = g_wo_t;
    const int K = 128, NC = 8;

    const int tid  = threadIdx.x;
    const int mblk = blockIdx.x;
    const int bt   = mblk >> 4;
    const int nloc = (mblk & 15) << 6;
    const int tm = tid & 15, tn = tid >> 4;
    const int m0 = tm << 2, o0 = tn << 3;
    const int bkk = tid >> 4, bj = tid & 15;

    u64 acc2[4][4];
#pragma unroll
    for (int i = 0; i < 4; i++)
#pragma unroll
        for (int j = 0; j < 4; j++) acc2[i][j] = 0ull;

    for (int idx = tid; idx < 1024; idx += 256) {
        int kk = idx & 15, m = idx >> 4;
        s_A[0][kk][m] = A[(bt * 1024 + nloc + m) * K + kk];
    }
    {
        float4 t0 = *(const float4*)&Wt[bkk * 128 + (bj << 2)];
        float4 t1 = *(const float4*)&Wt[bkk * 128 + 64 + (bj << 2)];
        *(float4*)&s_B[0][bkk][bj << 2] = t0;
        *(float4*)&s_B[0][bkk][64 + (bj << 2)] = t1;
    }
    __syncthreads();

    int buf = 0;
    for (int t = 0; t < NC; t++) {
        float pArow[4];
        float4 pB0, pB1;
        if (t < NC - 1) {
            int c0 = (t + 1) << 4;
#pragma unroll
            for (int ii = 0; ii < 4; ii++) {
                int idx = tid + (ii << 8);
                int kk = idx & 15, m = idx >> 4;
                pArow[ii] = A[(bt * 1024 + nloc + m) * K + c0 + kk];
            }
            pB0 = *(const float4*)&Wt[(c0 + bkk) * 128 + (bj << 2)];
            pB1 = *(const float4*)&Wt[(c0 + bkk) * 128 + 64 + (bj << 2)];
        }

#pragma unroll
        for (int kk = 0; kk < 16; kk++) {
            float4 a0 = *(const float4*)&s_A[buf][kk][m0];
            ulonglong2 b01 = *(const ulonglong2*)&s_B[buf][kk][o0];
            ulonglong2 b23 = *(const ulonglong2*)&s_B[buf][kk][o0 + 4];
            u64 ap[4];
            ap[0] = pack2(a0.x, a0.x); ap[1] = pack2(a0.y, a0.y);
            ap[2] = pack2(a0.z, a0.z); ap[3] = pack2(a0.w, a0.w);
#pragma unroll
            for (int i = 0; i < 4; i++) {
                ffma2(acc2[i][0], ap[i], b01.x);
                ffma2(acc2[i][1], ap[i], b01.y);
                ffma2(acc2[i][2], ap[i], b23.x);
                ffma2(acc2[i][3], ap[i], b23.y);
            }
        }

        if (t < NC - 1) {
            int nb = buf ^ 1;
#pragma unroll
            for (int ii = 0; ii < 4; ii++) {
                int idx = tid + (ii << 8);
                int kk = idx & 15, m = idx >> 4;
                s_A[nb][kk][m] = pArow[ii];
            }
            *(float4*)&s_B[nb][bkk][bj << 2] = pB0;
            *(float4*)&s_B[nb][bkk][64 + (bj << 2)] = pB1;
        }
        __syncthreads();
        buf ^= 1;
    }

    float f[4][8];
#pragma unroll
    for (int i = 0; i < 4; i++)
#pragma unroll
        for (int jp = 0; jp < 4; jp++)
            unpack2(acc2[i][jp], f[i][2 * jp], f[i][2 * jp + 1]);
#pragma unroll
    for (int j = 0; j < 8; j++) {
        float bb = bo[o0 + j];
        float4 t = {f[0][j] + bb, f[1][j] + bb, f[2][j] + bb, f[3][j] + bb};
        *(float4*)&g_fused[((bt << 7) + o0 + j) * 1024 + nloc + m0] = t;
    }
}

// ---------------------------------------------------------------------------
// Flash attention pass 1 (split-K x8), 2 queries/thread, 16-key tiles,
// no-max softmax with exp fused into the key loop (no score arrays).
// __launch_bounds__(128, 3): register diet for 3 blocks/SM.
// Grid: (4 qtiles, 4 heads, 64) = 1024 blocks x 128.
// ---------------------------------------------------------------------------
__global__ void __launch_bounds__(128, 3) attention_part_kernel()
{
    __shared__ __align__(16) float sK[2][16][32];
    __shared__ __align__(16) float sV[2][16][32];
    const int qt = blockIdx.x, h = blockIdx.y;
    const int bt = blockIdx.z >> 3, ck = blockIdx.z & 7;
    const int r = threadIdx.x;
    const int n0 = (qt << 8) + r;        // query row A
    const int n1 = n0 + 128;             // query row B
    const int kbase = ck << 7;           // 128 keys per chunk

    u64 qa[16], qb[16];
    {
        const ulonglong2* qp0 = (const ulonglong2*)&g_q[(bt * 1024 + n0) * 128 + (h << 5)];
        const ulonglong2* qp1 = (const ulonglong2*)&g_q[(bt * 1024 + n1) * 128 + (h << 5)];
#pragma unroll
        for (int i = 0; i < 8; i++) {
            ulonglong2 t0 = qp0[i], t1 = qp1[i];
            qa[2 * i]     = t0.x; qa[2 * i + 1] = t0.y;
            qb[2 * i]     = t1.x; qb[2 * i + 1] = t1.y;
        }
    }
    u64 oa[16], ob[16];
#pragma unroll
    for (int i = 0; i < 16; i++) { oa[i] = 0ull; ob[i] = 0ull; }
    float l0r = 0.f, l1r = 0.f;

    // staging: 16 rows x 8 float4 = 128 slots, one per thread
    const int skk = r >> 3, sj = r & 7;

    // prologue: tile 0
    ((float4*)sK[0][skk])[sj] =
        ((const float4*)&g_k[((bt << 10) + kbase + skk) * 128 + (h << 5)])[sj];
    ((float4*)sV[0][skk])[sj] =
        ((const float4*)&g_v[((bt << 10) + kbase + skk) * 128 + (h << 5)])[sj];
    __syncthreads();

    int buf = 0;
    for (int t = 0; t < 8; t++) {
        float4 pk, pv;
        if (t < 7) {
            int kt = kbase + ((t + 1) << 4);
            pk = ((const float4*)&g_k[((bt << 10) + kt + skk) * 128 + (h << 5)])[sj];
            pv = ((const float4*)&g_v[((bt << 10) + kt + skk) * 128 + (h << 5)])[sj];
        }

        // fused QK -> exp -> PV per key (no score arrays)
#pragma unroll
        for (int kk = 0; kk < 16; kk++) {
            const ulonglong2* kp = (const ulonglong2*)sK[buf][kk];
            u64 a0 = 0ull, a1 = 0ull, b0 = 0ull, b1 = 0ull;
#pragma unroll
            for (int i = 0; i < 8; i++) {
                ulonglong2 t2 = kp[i];
                ffma2(a0, qa[2 * i], t2.x);
                ffma2(a1, qa[2 * i + 1], t2.y);
                ffma2(b0, qb[2 * i], t2.x);
                ffma2(b1, qb[2 * i + 1], t2.y);
            }
            float lo, hi, s0, s1;
            u64 sa = add2(a0, a1);
            unpack2(sa, lo, hi); s0 = __expf(lo + hi);
            u64 sb = add2(b0, b1);
            unpack2(sb, lo, hi); s1 = __expf(lo + hi);
            l0r += s0; l1r += s1;

            const ulonglong2* vp = (const ulonglong2*)sV[buf][kk];
            u64 p0 = pack2(s0, s0);
            u64 p1 = pack2(s1, s1);
#pragma unroll
            for (int i = 0; i < 8; i++) {
                ulonglong2 t2 = vp[i];
                ffma2(oa[2 * i], p0, t2.x);
                ffma2(oa[2 * i + 1], p0, t2.y);
                ffma2(ob[2 * i], p1, t2.x);
                ffma2(ob[2 * i + 1], p1, t2.y);
            }
        }

        if (t < 7) {
            ((float4*)sK[buf ^ 1][skk])[sj] = pk;
            ((float4*)sV[buf ^ 1][skk])[sj] = pv;
        }
        __syncthreads();
        buf ^= 1;
    }

    // store partials for both queries: po layout [bt][h][ck][d][n]
    float* pob = g_po + ((((bt << 2) + h) << 3) + ck) * (32 * 1024);
#pragma unroll
    for (int p = 0; p < 16; p++) {
        float f0, f1;
        unpack2(oa[p], f0, f1);
        pob[(2 * p) * 1024 + n0]     = f0;
        pob[(2 * p + 1) * 1024 + n0] = f1;
        unpack2(ob[p], f0, f1);
        pob[(2 * p) * 1024 + n1]     = f0;
        pob[(2 * p + 1) * 1024 + n1] = f1;
    }
    float* pl = g_pl + ((((bt << 2) + h) << 3) + ck) * 1024;
    pl[n0] = l0r;
    pl[n1] = l1r;
}

// ---------------------------------------------------------------------------
// Merge split-K partials (8 chunks) -> attention output.
// ---------------------------------------------------------------------------
__global__ void __launch_bounds__(256) attention_merge_kernel()
{
    int idx = blockIdx.x * 256 + threadIdx.x;
    int n = idx & 1023, h = (idx >> 10) & 3, bt = idx >> 12;
    int rb = ((bt << 2) + h) << 3;

    float ls = 0.f;
#pragma unroll
    for (int c = 0; c < 8; c++)
        ls += g_pl[(rb + c) * 1024 + n];
    float inv = 1.f / ls;

    float acc[32];
#pragma unroll
    for (int d = 0; d < 32; d++) acc[d] = 0.f;
#pragma unroll
    for (int c = 0; c < 8; c++) {
        const float* po = g_po + (rb + c) * (32 * 1024) + n;
#pragma unroll
        for (int d = 0; d < 32; d++)
            acc[d] += po[d * 1024];
    }
    float4* dst = (float4*)&g_attn[(bt * 1024 + n) * 128 + (h << 5)];
#pragma unroll
    for (int j = 0; j < 8; j++) {
        float4 t = {acc[4 * j] * inv, acc[4 * j + 1] * inv,
                    acc[4 * j + 2] * inv, acc[4 * j + 3] * inv};
        dst[j] = t;
    }
}

// ---------------------------------------------------------------------------
// conv_out standalone wrapper (writes d_out). Grid (8, 16, 2).
// ---------------------------------------------------------------------------
__global__ void __launch_bounds__(256) conv_out_kernel(
    const float* __restrict__ ego, const float* __restrict__ b_out,
    float* __restrict__ out)
{
    __shared__ __align__(16) float s_in[16][18][34];
    __shared__ __align__(16) float s_w[16][9][8];
    conv_body<128, 144>(g_fused, ego, g_wout_t, b_out, out, 128,
                        blockIdx.x, blockIdx.y << 3, blockIdx.z << 4, s_in, s_w);
}

// ---------------------------------------------------------------------------
extern "C" void kernel_launch(void* const* d_in, const int* in_sizes, int n_in,
                              void* d_out, int out_size)
{
    const float* bev   = (const float*)d_in[0];
    const float* hd    = (const float*)d_in[1];
    const float* ego   = (const float*)d_in[2];
    const float* front = (const float*)d_in[3];
    const float* w_bev = (const float*)d_in[4];
    const float* b_bev = (const float*)d_in[5];
    const float* w_hd  = (const float*)d_in[6];
    const float* b_hd  = (const float*)d_in[7];
    const float* wq    = (const float*)d_in[8];
    const float* wk    = (const float*)d_in[9];
    const float* wv    = (const float*)d_in[10];
    const float* wo    = (const float*)d_in[11];
    const float* bo    = (const float*)d_in[12];
    const float* w_out = (const float*)d_in[13];
    const float* b_out = (const float*)d_in[14];
    float* out = (float*)d_out;

    transform_all_kernel<<<1904, 256>>>(wq, wk, wv, wo, w_bev, w_hd, w_out);
    frontend_kernel<<<dim3(8, 33, 2), 256>>>(bev, hd, ego, front, b_bev, b_hd);
    qkv_kernel<<<dim3(128, 2), 256>>>();
    attention_part_kernel<<<dim3(4, 4, 64), 128>>>();
    attention_merge_kernel<<<128, 256>>>();
    oproj_kernel<<<128, 256>>>(bo);
    conv_out_kernel<<<dim3(8, 16, 2), 256>>>(ego, b_out, out);
}